// round 1
// baseline (speedup 1.0000x reference)
#include <cuda_runtime.h>
#include <cuda_bf16.h>
#include <float.h>
#include <math.h>

// ---------------- problem constants ----------------
#define FEAT 1024
#define HID 256
#define MAXN 100000
#define KS 8   // K_SAMPLE

// ---------------- scratch (device globals; no allocation) ----------------
__device__ float g_x[(size_t)MAXN * HID];     // relu(h @ Wfc^T + b)
__device__ float g_pa[(size_t)MAXN * HID];    // x @ Wa^T
__device__ float g_pb[(size_t)MAXN * HID];    // x @ Wb^T
__device__ float g_scores[MAXN];
__device__ float g_pmax[256];
__device__ float g_mZ[2];                     // [0]=max
__device__ float g_pool_part[256 * HID];
__device__ float g_psum[256];
__device__ float g_M[HID];
__device__ int   g_topidx[2 * KS];

// ---------------- SGEMM: C[M,Nn] = A[M,K] @ B[Nn,K]^T  (both K-major) ------
// ACT==1: C = relu(C + bias[col])
template <int ACT>
__global__ __launch_bounds__(256) void sgemm_nt(
    const float* __restrict__ A, const float* __restrict__ B,
    const float* __restrict__ bias, float* __restrict__ C,
    int M, int Nn, int K)
{
    constexpr int BM = 128, BN = 128, BK = 16, TM = 8, TN = 8;
    __shared__ float As[BK][BM];
    __shared__ float Bs[BK][BN];

    const int tid = threadIdx.x;            // 256 threads
    const int tr = tid >> 4;                // 0..15
    const int tc = tid & 15;                // 0..15
    const int rowBase = blockIdx.y * BM;
    const int colBase = blockIdx.x * BN;

    float acc[TM][TN];
#pragma unroll
    for (int m = 0; m < TM; m++)
#pragma unroll
        for (int n = 0; n < TN; n++) acc[m][n] = 0.0f;

    for (int k0 = 0; k0 < K; k0 += BK) {
        // load A tile (BM x BK), transpose into As[k][row]
#pragma unroll
        for (int it = 0; it < 2; it++) {
            int t2 = tid + it * 256;        // 0..511
            int r = t2 >> 2;                // 0..127
            int c4 = (t2 & 3) * 4;          // 0,4,8,12
            int grow = rowBase + r;
            float4 v = make_float4(0.f, 0.f, 0.f, 0.f);
            if (grow < M)
                v = *reinterpret_cast<const float4*>(&A[(size_t)grow * K + k0 + c4]);
            As[c4 + 0][r] = v.x;
            As[c4 + 1][r] = v.y;
            As[c4 + 2][r] = v.z;
            As[c4 + 3][r] = v.w;
        }
        // load B tile (BN x BK), transpose into Bs[k][col]
#pragma unroll
        for (int it = 0; it < 2; it++) {
            int t2 = tid + it * 256;
            int r = t2 >> 2;
            int c4 = (t2 & 3) * 4;
            int gcol = colBase + r;
            float4 v = make_float4(0.f, 0.f, 0.f, 0.f);
            if (gcol < Nn)
                v = *reinterpret_cast<const float4*>(&B[(size_t)gcol * K + k0 + c4]);
            Bs[c4 + 0][r] = v.x;
            Bs[c4 + 1][r] = v.y;
            Bs[c4 + 2][r] = v.z;
            Bs[c4 + 3][r] = v.w;
        }
        __syncthreads();

#pragma unroll
        for (int k = 0; k < BK; k++) {
            float rm[TM], rn[TN];
#pragma unroll
            for (int m = 0; m < TM; m++) rm[m] = As[k][tr * TM + m];
#pragma unroll
            for (int n = 0; n < TN; n++) rn[n] = Bs[k][tc * TN + n];
#pragma unroll
            for (int m = 0; m < TM; m++)
#pragma unroll
                for (int n = 0; n < TN; n++) acc[m][n] = fmaf(rm[m], rn[n], acc[m][n]);
        }
        __syncthreads();
    }

#pragma unroll
    for (int m = 0; m < TM; m++) {
        int grow = rowBase + tr * TM + m;
        if (grow >= M) continue;
#pragma unroll
        for (int n = 0; n < TN; n++) {
            int gc = colBase + tc * TN + n;
            if (gc >= Nn) continue;
            float v = acc[m][n];
            if (ACT == 1) v = fmaxf(v + bias[gc], 0.0f);
            C[(size_t)grow * Nn + gc] = v;
        }
    }
}

// ---------------- attention score: s_i = Wc . (tanh(pa+ba) * sigmoid(pb+bb)) + bc
__global__ void attn_score(const float* __restrict__ Pa, const float* __restrict__ Pb,
                           const float* __restrict__ ba, const float* __restrict__ bb,
                           const float* __restrict__ Wc, const float* __restrict__ bc,
                           float* __restrict__ scores, int N)
{
    int gwarp = (blockIdx.x * blockDim.x + threadIdx.x) >> 5;
    int lane = threadIdx.x & 31;
    if (gwarp >= N) return;
    const float* pa = Pa + (size_t)gwarp * HID;
    const float* pb = Pb + (size_t)gwarp * HID;
    float partial = 0.0f;
#pragma unroll
    for (int c = lane; c < HID; c += 32) {
        float a = tanhf(pa[c] + ba[c]);
        float gv = pb[c] + bb[c];
        float g = 1.0f / (1.0f + __expf(-gv));
        partial = fmaf(a * g, Wc[c], partial);
    }
#pragma unroll
    for (int off = 16; off >= 1; off >>= 1)
        partial += __shfl_xor_sync(0xffffffffu, partial, off);
    if (lane == 0) scores[gwarp] = partial + bc[0];
}

// ---------------- reductions ----------------
__global__ void reduce_max_k(const float* __restrict__ s, int N, float* __restrict__ pmax)
{
    __shared__ float sm[256];
    int chunk = (N + gridDim.x - 1) / gridDim.x;
    int start = blockIdx.x * chunk;
    int end = min(start + chunk, N);
    float m = -FLT_MAX;
    for (int i = start + threadIdx.x; i < end; i += blockDim.x) m = fmaxf(m, s[i]);
    sm[threadIdx.x] = m;
    __syncthreads();
    for (int str = 128; str > 0; str >>= 1) {
        if (threadIdx.x < str) sm[threadIdx.x] = fmaxf(sm[threadIdx.x], sm[threadIdx.x + str]);
        __syncthreads();
    }
    if (threadIdx.x == 0) pmax[blockIdx.x] = sm[0];
}

__global__ void finalize_max_k(const float* __restrict__ pmax, float* __restrict__ mZ)
{
    __shared__ float sm[256];
    sm[threadIdx.x] = pmax[threadIdx.x];
    __syncthreads();
    for (int str = 128; str > 0; str >>= 1) {
        if (threadIdx.x < str) sm[threadIdx.x] = fmaxf(sm[threadIdx.x], sm[threadIdx.x + str]);
        __syncthreads();
    }
    if (threadIdx.x == 0) mZ[0] = sm[0];
}

// ---------------- weighted pooling partials: part[b][j] = sum_i exp(s_i-m) x[i][j]
__global__ void pool_partial_k(const float* __restrict__ x, const float* __restrict__ s,
                               const float* __restrict__ mZ, int N,
                               float* __restrict__ part, float* __restrict__ psum)
{
    const float m = mZ[0];
    int chunk = (N + gridDim.x - 1) / gridDim.x;
    int start = blockIdx.x * chunk;
    int end = min(start + chunk, N);
    int j = threadIdx.x;  // 256 = HID
    float acc = 0.0f, wsum = 0.0f;
    for (int i = start; i < end; i++) {
        float w = __expf(s[i] - m);
        acc = fmaf(w, x[(size_t)i * HID + j], acc);
        wsum += w;
    }
    part[blockIdx.x * HID + j] = acc;
    if (j == 0) psum[blockIdx.x] = wsum;
}

__global__ void pool_final_k(const float* __restrict__ part, const float* __restrict__ psum,
                             float* __restrict__ Mout)
{
    __shared__ float sz[256];
    int j = threadIdx.x;
    float acc = 0.0f;
    for (int b = 0; b < 256; b++) acc += part[b * HID + j];
    sz[j] = psum[j];
    __syncthreads();
    for (int str = 128; str > 0; str >>= 1) {
        if (j < str) sz[j] += sz[j + str];
        __syncthreads();
    }
    Mout[j] = acc / sz[0];
}

// ---------------- top-8 / bottom-8 selection (single block, 256 threads) ----
__global__ void topk_kernel(const float* __restrict__ s, int N, int* __restrict__ out_idx)
{
    const int tid = threadIdx.x;
    float tv[KS], bv[KS];
    int ti[KS], bi[KS];
#pragma unroll
    for (int k = 0; k < KS; k++) { tv[k] = -FLT_MAX; ti[k] = 0; bv[k] = FLT_MAX; bi[k] = 0; }

    for (int i = tid; i < N; i += 256) {
        float v = s[i];
        if (v > tv[KS - 1]) {
            tv[KS - 1] = v; ti[KS - 1] = i;
            for (int j = KS - 1; j > 0; j--) {
                if (tv[j] > tv[j - 1]) {
                    float fv = tv[j]; tv[j] = tv[j - 1]; tv[j - 1] = fv;
                    int fi = ti[j]; ti[j] = ti[j - 1]; ti[j - 1] = fi;
                } else break;
            }
        }
        if (v < bv[KS - 1]) {
            bv[KS - 1] = v; bi[KS - 1] = i;
            for (int j = KS - 1; j > 0; j--) {
                if (bv[j] < bv[j - 1]) {
                    float fv = bv[j]; bv[j] = bv[j - 1]; bv[j - 1] = fv;
                    int fi = bi[j]; bi[j] = bi[j - 1]; bi[j - 1] = fi;
                } else break;
            }
        }
    }

    __shared__ float cv[256 * KS];
    __shared__ int   ci[256 * KS];
    __shared__ float rv[256];
    __shared__ int   rs[256];

    // ---- top 8 ----
#pragma unroll
    for (int k = 0; k < KS; k++) { cv[tid * KS + k] = tv[k]; ci[tid * KS + k] = ti[k]; }
    __syncthreads();
    for (int pass = 0; pass < KS; pass++) {
        float bestv = -FLT_MAX; int bestslot = tid * KS;
#pragma unroll
        for (int k = 0; k < KS; k++) {
            int sl = tid * KS + k;
            if (cv[sl] > bestv) { bestv = cv[sl]; bestslot = sl; }
        }
        rv[tid] = bestv; rs[tid] = bestslot;
        __syncthreads();
        for (int str = 128; str > 0; str >>= 1) {
            if (tid < str && rv[tid + str] > rv[tid]) { rv[tid] = rv[tid + str]; rs[tid] = rs[tid + str]; }
            __syncthreads();
        }
        if (tid == 0) { out_idx[pass] = ci[rs[0]]; cv[rs[0]] = -FLT_MAX; }
        __syncthreads();
    }

    // ---- bottom 8 ----
#pragma unroll
    for (int k = 0; k < KS; k++) { cv[tid * KS + k] = bv[k]; ci[tid * KS + k] = bi[k]; }
    __syncthreads();
    for (int pass = 0; pass < KS; pass++) {
        float bestv = FLT_MAX; int bestslot = tid * KS;
#pragma unroll
        for (int k = 0; k < KS; k++) {
            int sl = tid * KS + k;
            if (cv[sl] < bestv) { bestv = cv[sl]; bestslot = sl; }
        }
        rv[tid] = bestv; rs[tid] = bestslot;
        __syncthreads();
        for (int str = 128; str > 0; str >>= 1) {
            if (tid < str && rv[tid + str] < rv[tid]) { rv[tid] = rv[tid + str]; rs[tid] = rs[tid + str]; }
            __syncthreads();
        }
        if (tid == 0) { out_idx[KS + pass] = ci[rs[0]]; cv[rs[0]] = FLT_MAX; }
        __syncthreads();
    }
}

// ---------------- final tiny kernel: bag classifier + instance SVM loss -----
__global__ void final_kernel(const float* __restrict__ Mv,
                             const float* __restrict__ W_cls, const float* __restrict__ b_cls,
                             const float* __restrict__ W_inst, const float* __restrict__ b_inst,
                             const int* __restrict__ label_p,
                             const float* __restrict__ xbuf, const int* __restrict__ top_idx,
                             float* __restrict__ out)
{
    int lane = threadIdx.x;  // 32 threads
    int label = label_p[0];
    float my = 0.0f;
    if (lane < 2 * KS) {
        int id = top_idx[lane];
        const float* xr = xbuf + (size_t)id * HID;
        const float* w0 = W_inst + (size_t)(label * 2 + 0) * HID;
        const float* w1 = W_inst + (size_t)(label * 2 + 1) * HID;
        float s0 = b_inst[label * 2 + 0], s1 = b_inst[label * 2 + 1];
        for (int j = 0; j < HID; j++) {
            float xv = xr[j];
            s0 = fmaf(xv, w0[j], s0);
            s1 = fmaf(xv, w1[j], s1);
        }
        int t = (lane < KS) ? 1 : 0;
        float a0 = s0 + ((t == 0) ? 0.0f : 1.0f);
        float a1 = s1 + ((t == 1) ? 0.0f : 1.0f);
        float mm = fmaxf(a0, a1);
        float lse = mm + logf(expf(a0 - mm) + expf(a1 - mm));
        float sy = (t == 1) ? s1 : s0;
        my = lse - sy;
    }
#pragma unroll
    for (int off = 16; off >= 1; off >>= 1)
        my += __shfl_xor_sync(0xffffffffu, my, off);

    if (lane == 0) {
        float loss = my / (float)(2 * KS);
        float l0 = b_cls[0], l1 = b_cls[1];
        for (int j = 0; j < HID; j++) {
            float m = Mv[j];
            l0 = fmaf(W_cls[j], m, l0);
            l1 = fmaf(W_cls[HID + j], m, l1);
        }
        float mm = fmaxf(l0, l1);
        float e0 = expf(l0 - mm), e1 = expf(l1 - mm);
        float Z = e0 + e1;
        out[0] = l0;
        out[1] = l1;
        out[2] = e0 / Z;
        out[3] = e1 / Z;
        out[4] = (l1 > l0) ? 1.0f : 0.0f;  // argmax, first-index on ties
        out[5] = loss;
    }
}

// ---------------- launch ----------------
extern "C" void kernel_launch(void* const* d_in, const int* in_sizes, int n_in,
                              void* d_out, int out_size)
{
    const float* h     = (const float*)d_in[0];
    const int*   label = (const int*)d_in[1];
    const float* W_fc  = (const float*)d_in[2];
    const float* b_fc  = (const float*)d_in[3];
    const float* Wa    = (const float*)d_in[4];
    const float* ba    = (const float*)d_in[5];
    const float* Wb    = (const float*)d_in[6];
    const float* bb    = (const float*)d_in[7];
    const float* Wc    = (const float*)d_in[8];
    const float* bc    = (const float*)d_in[9];
    const float* W_cls = (const float*)d_in[10];
    const float* b_cls = (const float*)d_in[11];
    const float* W_inst= (const float*)d_in[12];
    const float* b_inst= (const float*)d_in[13];

    int N = in_sizes[0] / FEAT;

    float *px, *ppa, *ppb, *pscores, *ppmax, *pmZ, *ppart, *ppsum, *pM;
    int *ptop;
    cudaGetSymbolAddress((void**)&px, g_x);
    cudaGetSymbolAddress((void**)&ppa, g_pa);
    cudaGetSymbolAddress((void**)&ppb, g_pb);
    cudaGetSymbolAddress((void**)&pscores, g_scores);
    cudaGetSymbolAddress((void**)&ppmax, g_pmax);
    cudaGetSymbolAddress((void**)&pmZ, g_mZ);
    cudaGetSymbolAddress((void**)&ppart, g_pool_part);
    cudaGetSymbolAddress((void**)&ppsum, g_psum);
    cudaGetSymbolAddress((void**)&pM, g_M);
    cudaGetSymbolAddress((void**)&ptop, g_topidx);

    dim3 gemmGrid((HID + 127) / 128, (N + 127) / 128);

    // x = relu(h @ Wfc^T + b_fc)
    sgemm_nt<1><<<gemmGrid, 256>>>(h, W_fc, b_fc, px, N, HID, FEAT);
    // pre-activations for attention
    sgemm_nt<0><<<gemmGrid, 256>>>(px, Wa, nullptr, ppa, N, HID, HID);
    sgemm_nt<0><<<gemmGrid, 256>>>(px, Wb, nullptr, ppb, N, HID, HID);
    // per-instance attention score
    attn_score<<<(N * 32 + 255) / 256, 256>>>(ppa, ppb, ba, bb, Wc, bc, pscores, N);
    // softmax denominator pieces + pooling
    reduce_max_k<<<256, 256>>>(pscores, N, ppmax);
    finalize_max_k<<<1, 256>>>(ppmax, pmZ);
    pool_partial_k<<<256, 256>>>(px, pscores, pmZ, N, ppart, ppsum);
    pool_final_k<<<1, 256>>>(ppart, ppsum, pM);
    // top-8 / bottom-8 instance selection
    topk_kernel<<<1, 256>>>(pscores, N, ptop);
    // bag logits + probs + argmax + instance SVM loss
    final_kernel<<<1, 32>>>(pM, W_cls, b_cls, W_inst, b_inst, label, px, ptop,
                            (float*)d_out);
}

// round 4
// speedup vs baseline: 2.0001x; 2.0001x over previous
#include <cuda_runtime.h>
#include <cuda_bf16.h>
#include <float.h>
#include <math.h>
#include <cstdint>

// ---------------- problem constants ----------------
#define FEAT 1024
#define HID 256
#define MAXN 100000
#define KS 8   // K_SAMPLE

// ---------------- scratch (device globals; no allocation) ----------------
__device__ float g_x[(size_t)MAXN * HID];       // relu(h @ Wfc^T + b)
__device__ float g_spart[4 * (size_t)MAXN];     // partial attention scores (4 col-blocks)
__device__ float g_pmax[256];
__device__ float g_mZ[2];
__device__ float g_pool_part[256 * HID];
__device__ float g_psum[256];
__device__ float g_M[HID];
__device__ int   g_topidx[2 * KS];

// ---------------- helpers ----------------
// split fp32 pair into bf16 hi-pair and lo-pair (packed u32, low element = smaller k)
__device__ __forceinline__ void split_pack2(float v0, float v1, uint32_t& h, uint32_t& l) {
    uint32_t hu;
    asm("cvt.rn.bf16x2.f32 %0, %1, %2;" : "=r"(hu) : "f"(v1), "f"(v0));
    float h0 = __uint_as_float(hu << 16);
    float h1 = __uint_as_float(hu & 0xFFFF0000u);
    float r0 = v0 - h0, r1 = v1 - h1;
    uint32_t lu;
    asm("cvt.rn.bf16x2.f32 %0, %1, %2;" : "=r"(lu) : "f"(r1), "f"(r0));
    h = hu; l = lu;
}

// m16n8k16 row.col bf16 MMA, fp32 accumulate (sm_80+, no 'a' features)
__device__ __forceinline__ void mma_bf16(float* c, uint32_t a0, uint32_t a1,
                                         uint32_t a2, uint32_t a3,
                                         uint32_t b0, uint32_t b1) {
    asm volatile(
        "mma.sync.aligned.m16n8k16.row.col.f32.bf16.bf16.f32 "
        "{%0,%1,%2,%3}, {%4,%5,%6,%7}, {%8,%9}, {%0,%1,%2,%3};\n"
        : "+f"(c[0]), "+f"(c[1]), "+f"(c[2]), "+f"(c[3])
        : "r"(a0), "r"(a1), "r"(a2), "r"(a3), "r"(b0), "r"(b1));
}

__device__ __forceinline__ float load_score(const float* __restrict__ p, int i) {
    return p[i] + p[MAXN + i] + p[2 * MAXN + i] + p[3 * MAXN + i];
}

// smem record layout: per row (192B stride), per k16-step s (64B), per t (16B):
//   {hi(pair p), hi(pair p+4), lo(pair p), lo(pair p+4)},  p = 8s+t, pair = k/2
#define ROWSTRIDE 192
#define A_TILE_B (128 * ROWSTRIDE)       // 24576
#define STAGE_B  (2 * A_TILE_B)          // 49152 (A then B)
#define SMEM_TOT (2 * STAGE_B)           // 98304

// ================= bf16-split mma.sync GEMM =================
// C[128 x 128] block of A[M,K] @ B[*,K]^T.
// EPI=0: (GEMM1) out[row*256 + cb*128+col] = relu(C + bias[.]), B rows = B0[cb*128 + r]
// EPI=1: (GEMM2) B rows: r<64 -> Wa(B0)[cb*64+r], else Wb(B1)[cb*64+r-64];
//        epilogue: partial score over 64 attn cols -> out[cb*MAXN + row]
template <int EPI>
__global__ void __launch_bounds__(256, 1)
gemm_mma(const float* __restrict__ A, const float* __restrict__ B0,
         const float* __restrict__ B1, const float* __restrict__ bias,
         const float* __restrict__ ba, const float* __restrict__ bb,
         const float* __restrict__ Wc,
         float* __restrict__ out, int M, int K)
{
    extern __shared__ __align__(16) char smem[];
    const int tid = threadIdx.x;
    const int lane = tid & 31;
    const int wid = tid >> 5;
    const int wm = wid & 3;         // 4 row-slices of 32
    const int wn = wid >> 2;        // 2 col-slices of 64
    const int g = lane >> 2;        // 0..7
    const int tq = lane & 3;        // 0..3
    const int cb = blockIdx.x;
    const int rowbase = blockIdx.y * 128;
    const int NIT = K >> 5;

    float acc[2][8][4];
#pragma unroll
    for (int mt = 0; mt < 2; mt++)
#pragma unroll
        for (int nt = 0; nt < 8; nt++)
#pragma unroll
            for (int j = 0; j < 4; j++) acc[mt][nt][j] = 0.f;

    // producer-held values: 4 A-records + 4 B-records, 4 floats each
    float ha[4][4], hb[4][4];

    // ---- producer: load records for iteration `it` into ha/hb ----
    auto load_iter = [&](int it) {
        const int k0 = it << 5;
#pragma unroll
        for (int q = 0; q < 4; q++) {
            int idx = q * 256 + tid;           // 0..1023
            int r = idx >> 3;
            int s = (idx >> 2) & 1;
            int t = idx & 3;
            int kf = k0 + 16 * s + 2 * t;
            // A record
            int grow = rowbase + r;
            if (grow < M) {
                const float* src = A + (size_t)grow * K + kf;
                float2 u = *(const float2*)(src);
                float2 v = *(const float2*)(src + 8);
                ha[q][0] = u.x; ha[q][1] = u.y; ha[q][2] = v.x; ha[q][3] = v.y;
            } else {
                ha[q][0] = ha[q][1] = ha[q][2] = ha[q][3] = 0.f;
            }
            // B record
            const float* brow;
            if (EPI == 0) {
                brow = B0 + (size_t)(cb * 128 + r) * K;
            } else {
                int c = cb * 64 + (r & 63);
                brow = ((r < 64) ? B0 : B1) + (size_t)c * K;
            }
            float2 u = *(const float2*)(brow + kf);
            float2 v = *(const float2*)(brow + kf + 8);
            hb[q][0] = u.x; hb[q][1] = u.y; hb[q][2] = v.x; hb[q][3] = v.y;
        }
    };
    auto store_iter = [&](int stage) {
        char* As = smem + stage * STAGE_B;
        char* Bs = As + A_TILE_B;
#pragma unroll
        for (int q = 0; q < 4; q++) {
            int idx = q * 256 + tid;
            int r = idx >> 3;
            int s = (idx >> 2) & 1;
            int t = idx & 3;
            uint32_t h0, l0, h1, l1;
            split_pack2(ha[q][0], ha[q][1], h0, l0);
            split_pack2(ha[q][2], ha[q][3], h1, l1);
            *(uint4*)(As + r * ROWSTRIDE + s * 64 + t * 16) = make_uint4(h0, h1, l0, l1);
            split_pack2(hb[q][0], hb[q][1], h0, l0);
            split_pack2(hb[q][2], hb[q][3], h1, l1);
            *(uint4*)(Bs + r * ROWSTRIDE + s * 64 + t * 16) = make_uint4(h0, h1, l0, l1);
        }
    };

    load_iter(0);
    store_iter(0);
    __syncthreads();

    for (int it = 0; it < NIT; it++) {
        if (it + 1 < NIT) load_iter(it + 1);

        // ---- compute on stage it&1 ----
        char* As = smem + (it & 1) * STAGE_B;
        char* Bs = As + A_TILE_B;
#pragma unroll
        for (int s = 0; s < 2; s++) {
            uint4 af[2][2];
#pragma unroll
            for (int mt = 0; mt < 2; mt++) {
                int r0 = wm * 32 + mt * 16 + g;
                af[mt][0] = *(const uint4*)(As + r0 * ROWSTRIDE + s * 64 + tq * 16);
                af[mt][1] = *(const uint4*)(As + (r0 + 8) * ROWSTRIDE + s * 64 + tq * 16);
            }
#pragma unroll
            for (int nt = 0; nt < 8; nt++) {
                int nr = wn * 64 + nt * 8 + g;
                uint4 bf = *(const uint4*)(Bs + nr * ROWSTRIDE + s * 64 + tq * 16);
#pragma unroll
                for (int mt = 0; mt < 2; mt++) {
                    // af[mt][0]={a0h,a2h,a0l,a2l}  af[mt][1]={a1h,a3h,a1l,a3l}
                    // bf = {b0h,b1h,b0l,b1l}
                    mma_bf16(acc[mt][nt], af[mt][0].x, af[mt][1].x, af[mt][0].y, af[mt][1].y, bf.x, bf.y);
                    mma_bf16(acc[mt][nt], af[mt][0].x, af[mt][1].x, af[mt][0].y, af[mt][1].y, bf.z, bf.w);
                    mma_bf16(acc[mt][nt], af[mt][0].z, af[mt][1].z, af[mt][0].w, af[mt][1].w, bf.x, bf.y);
                }
            }
        }

        if (it + 1 < NIT) store_iter((it + 1) & 1);
        __syncthreads();
    }

    if (EPI == 0) {
        // relu(C + bias) -> out[row*256 + cb*128 + col]
#pragma unroll
        for (int mt = 0; mt < 2; mt++) {
            int gr = rowbase + wm * 32 + mt * 16 + g;
#pragma unroll
            for (int nt = 0; nt < 8; nt++) {
                int col = cb * 128 + wn * 64 + nt * 8 + tq * 2;
                float b0v = __ldg(&bias[col]);
                float b1v = __ldg(&bias[col + 1]);
                if (gr < M) {
                    float2 v = make_float2(fmaxf(acc[mt][nt][0] + b0v, 0.f),
                                           fmaxf(acc[mt][nt][1] + b1v, 0.f));
                    *(float2*)(out + (size_t)gr * 256 + col) = v;
                }
                if (gr + 8 < M) {
                    float2 v = make_float2(fmaxf(acc[mt][nt][2] + b0v, 0.f),
                                           fmaxf(acc[mt][nt][3] + b1v, 0.f));
                    *(float2*)(out + (size_t)(gr + 8) * 256 + col) = v;
                }
            }
        }
    } else {
        // stash 128x128 tile to smem, then per-row partial attention score
        float (*Sc)[132] = (float (*)[132])smem;
#pragma unroll
        for (int mt = 0; mt < 2; mt++) {
            int lr = wm * 32 + mt * 16 + g;
#pragma unroll
            for (int nt = 0; nt < 8; nt++) {
                int lc = wn * 64 + nt * 8 + tq * 2;
                Sc[lr][lc]     = acc[mt][nt][0];
                Sc[lr][lc + 1] = acc[mt][nt][1];
                Sc[lr + 8][lc]     = acc[mt][nt][2];
                Sc[lr + 8][lc + 1] = acc[mt][nt][3];
            }
        }
        __syncthreads();
        int r = wid * 16 + (lane >> 1);
        int half = lane & 1;
        float sum = 0.f;
#pragma unroll
        for (int j = 0; j < 32; j++) {
            int c = half + 2 * j;
            float va = Sc[r][c] + __ldg(&ba[cb * 64 + c]);
            float vb = Sc[r][c + 64] + __ldg(&bb[cb * 64 + c]);
            float tv = tanhf(va);
            float gv = 1.0f / (1.0f + __expf(-vb));
            sum = fmaf(tv * gv, __ldg(&Wc[cb * 64 + c]), sum);
        }
        sum += __shfl_xor_sync(0xffffffffu, sum, 1);
        int gr = rowbase + r;
        if (half == 0 && gr < M) out[(size_t)cb * MAXN + gr] = sum;
    }
}

// ---------------- reductions (over composed scores) ----------------
__global__ void reduce_max_k(const float* __restrict__ sp, int N, float* __restrict__ pmax)
{
    __shared__ float sm[256];
    int chunk = (N + gridDim.x - 1) / gridDim.x;
    int start = blockIdx.x * chunk;
    int end = min(start + chunk, N);
    float m = -FLT_MAX;
    for (int i = start + threadIdx.x; i < end; i += blockDim.x)
        m = fmaxf(m, load_score(sp, i));
    sm[threadIdx.x] = m;
    __syncthreads();
    for (int str = 128; str > 0; str >>= 1) {
        if (threadIdx.x < str) sm[threadIdx.x] = fmaxf(sm[threadIdx.x], sm[threadIdx.x + str]);
        __syncthreads();
    }
    if (threadIdx.x == 0) pmax[blockIdx.x] = sm[0];
}

__global__ void finalize_max_k(const float* __restrict__ pmax, float* __restrict__ mZ)
{
    __shared__ float sm[256];
    sm[threadIdx.x] = pmax[threadIdx.x];
    __syncthreads();
    for (int str = 128; str > 0; str >>= 1) {
        if (threadIdx.x < str) sm[threadIdx.x] = fmaxf(sm[threadIdx.x], sm[threadIdx.x + str]);
        __syncthreads();
    }
    if (threadIdx.x == 0) mZ[0] = sm[0];
}

__global__ void pool_partial_k(const float* __restrict__ x, const float* __restrict__ sp,
                               const float* __restrict__ mZ, int N,
                               float* __restrict__ part, float* __restrict__ psum)
{
    const float m = mZ[0];
    int chunk = (N + gridDim.x - 1) / gridDim.x;
    int start = blockIdx.x * chunk;
    int end = min(start + chunk, N);
    int j = threadIdx.x;  // 256 = HID
    float acc = 0.0f, wsum = 0.0f;
    for (int i = start; i < end; i++) {
        float w = __expf(load_score(sp, i) - m);
        acc = fmaf(w, x[(size_t)i * HID + j], acc);
        wsum += w;
    }
    part[blockIdx.x * HID + j] = acc;
    if (j == 0) psum[blockIdx.x] = wsum;
}

__global__ void pool_final_k(const float* __restrict__ part, const float* __restrict__ psum,
                             float* __restrict__ Mout)
{
    __shared__ float sz[256];
    int j = threadIdx.x;
    float acc = 0.0f;
    for (int b = 0; b < 256; b++) acc += part[b * HID + j];
    sz[j] = psum[j];
    __syncthreads();
    for (int str = 128; str > 0; str >>= 1) {
        if (j < str) sz[j] += sz[j + str];
        __syncthreads();
    }
    Mout[j] = acc / sz[0];
}

// ---------------- top-8 / bottom-8 selection ----
__global__ void topk_kernel(const float* __restrict__ sp, int N, int* __restrict__ out_idx)
{
    const int tid = threadIdx.x;
    float tv[KS], bv[KS];
    int ti[KS], bi[KS];
#pragma unroll
    for (int k = 0; k < KS; k++) { tv[k] = -FLT_MAX; ti[k] = 0; bv[k] = FLT_MAX; bi[k] = 0; }

    for (int i = tid; i < N; i += 256) {
        float v = load_score(sp, i);
        if (v > tv[KS - 1]) {
            tv[KS - 1] = v; ti[KS - 1] = i;
            for (int j = KS - 1; j > 0; j--) {
                if (tv[j] > tv[j - 1]) {
                    float fv = tv[j]; tv[j] = tv[j - 1]; tv[j - 1] = fv;
                    int fi = ti[j]; ti[j] = ti[j - 1]; ti[j - 1] = fi;
                } else break;
            }
        }
        if (v < bv[KS - 1]) {
            bv[KS - 1] = v; bi[KS - 1] = i;
            for (int j = KS - 1; j > 0; j--) {
                if (bv[j] < bv[j - 1]) {
                    float fv = bv[j]; bv[j] = bv[j - 1]; bv[j - 1] = fv;
                    int fi = bi[j]; bi[j] = bi[j - 1]; bi[j - 1] = fi;
                } else break;
            }
        }
    }

    __shared__ float cv[256 * KS];
    __shared__ int   ci[256 * KS];
    __shared__ float rv[256];
    __shared__ int   rs[256];

#pragma unroll
    for (int k = 0; k < KS; k++) { cv[tid * KS + k] = tv[k]; ci[tid * KS + k] = ti[k]; }
    __syncthreads();
    for (int pass = 0; pass < KS; pass++) {
        float bestv = -FLT_MAX; int bestslot = tid * KS;
#pragma unroll
        for (int k = 0; k < KS; k++) {
            int sl = tid * KS + k;
            if (cv[sl] > bestv) { bestv = cv[sl]; bestslot = sl; }
        }
        rv[tid] = bestv; rs[tid] = bestslot;
        __syncthreads();
        for (int str = 128; str > 0; str >>= 1) {
            if (tid < str && rv[tid + str] > rv[tid]) { rv[tid] = rv[tid + str]; rs[tid] = rs[tid + str]; }
            __syncthreads();
        }
        if (tid == 0) { out_idx[pass] = ci[rs[0]]; cv[rs[0]] = -FLT_MAX; }
        __syncthreads();
    }

#pragma unroll
    for (int k = 0; k < KS; k++) { cv[tid * KS + k] = bv[k]; ci[tid * KS + k] = bi[k]; }
    __syncthreads();
    for (int pass = 0; pass < KS; pass++) {
        float bestv = FLT_MAX; int bestslot = tid * KS;
#pragma unroll
        for (int k = 0; k < KS; k++) {
            int sl = tid * KS + k;
            if (cv[sl] < bestv) { bestv = cv[sl]; bestslot = sl; }
        }
        rv[tid] = bestv; rs[tid] = bestslot;
        __syncthreads();
        for (int str = 128; str > 0; str >>= 1) {
            if (tid < str && rv[tid + str] < rv[tid]) { rv[tid] = rv[tid + str]; rs[tid] = rs[tid + str]; }
            __syncthreads();
        }
        if (tid == 0) { out_idx[KS + pass] = ci[rs[0]]; cv[rs[0]] = FLT_MAX; }
        __syncthreads();
    }
}

// ---------------- final tiny kernel ----------------
__global__ void final_kernel(const float* __restrict__ Mv,
                             const float* __restrict__ W_cls, const float* __restrict__ b_cls,
                             const float* __restrict__ W_inst, const float* __restrict__ b_inst,
                             const int* __restrict__ label_p,
                             const float* __restrict__ xbuf, const int* __restrict__ top_idx,
                             float* __restrict__ out)
{
    int lane = threadIdx.x;  // 32 threads
    int label = label_p[0];
    float my = 0.0f;
    if (lane < 2 * KS) {
        int id = top_idx[lane];
        const float* xr = xbuf + (size_t)id * HID;
        const float* w0 = W_inst + (size_t)(label * 2 + 0) * HID;
        const float* w1 = W_inst + (size_t)(label * 2 + 1) * HID;
        float s0 = b_inst[label * 2 + 0], s1 = b_inst[label * 2 + 1];
        for (int j = 0; j < HID; j++) {
            float xv = xr[j];
            s0 = fmaf(xv, w0[j], s0);
            s1 = fmaf(xv, w1[j], s1);
        }
        int t = (lane < KS) ? 1 : 0;
        float a0 = s0 + ((t == 0) ? 0.0f : 1.0f);
        float a1 = s1 + ((t == 1) ? 0.0f : 1.0f);
        float mm = fmaxf(a0, a1);
        float lse = mm + logf(expf(a0 - mm) + expf(a1 - mm));
        float sy = (t == 1) ? s1 : s0;
        my = lse - sy;
    }
#pragma unroll
    for (int off = 16; off >= 1; off >>= 1)
        my += __shfl_xor_sync(0xffffffffu, my, off);

    if (lane == 0) {
        float loss = my / (float)(2 * KS);
        float l0 = b_cls[0], l1 = b_cls[1];
        for (int j = 0; j < HID; j++) {
            float m = Mv[j];
            l0 = fmaf(W_cls[j], m, l0);
            l1 = fmaf(W_cls[HID + j], m, l1);
        }
        float mm = fmaxf(l0, l1);
        float e0 = expf(l0 - mm), e1 = expf(l1 - mm);
        float Z = e0 + e1;
        out[0] = l0;
        out[1] = l1;
        out[2] = e0 / Z;
        out[3] = e1 / Z;
        out[4] = (l1 > l0) ? 1.0f : 0.0f;
        out[5] = loss;
    }
}

// ---------------- launch ----------------
extern "C" void kernel_launch(void* const* d_in, const int* in_sizes, int n_in,
                              void* d_out, int out_size)
{
    const float* h     = (const float*)d_in[0];
    const int*   label = (const int*)d_in[1];
    const float* W_fc  = (const float*)d_in[2];
    const float* b_fc  = (const float*)d_in[3];
    const float* Wa    = (const float*)d_in[4];
    const float* ba    = (const float*)d_in[5];
    const float* Wb    = (const float*)d_in[6];
    const float* bb    = (const float*)d_in[7];
    const float* Wc    = (const float*)d_in[8];
    const float* bc    = (const float*)d_in[9];  // softmax-invariant; unused downstream
    const float* W_cls = (const float*)d_in[10];
    const float* b_cls = (const float*)d_in[11];
    const float* W_inst= (const float*)d_in[12];
    const float* b_inst= (const float*)d_in[13];
    (void)bc;

    int N = in_sizes[0] / FEAT;

    float *px, *pspart, *ppmax, *pmZ, *ppart, *ppsum, *pM;
    int *ptop;
    cudaGetSymbolAddress((void**)&px, g_x);
    cudaGetSymbolAddress((void**)&pspart, g_spart);
    cudaGetSymbolAddress((void**)&ppmax, g_pmax);
    cudaGetSymbolAddress((void**)&pmZ, g_mZ);
    cudaGetSymbolAddress((void**)&ppart, g_pool_part);
    cudaGetSymbolAddress((void**)&ppsum, g_psum);
    cudaGetSymbolAddress((void**)&pM, g_M);
    cudaGetSymbolAddress((void**)&ptop, g_topidx);

    int rbs = (N + 127) / 128;

    // K1: x = relu(h @ Wfc^T + b_fc); N=256 -> 2 col-blocks
    cudaFuncSetAttribute(gemm_mma<0>, cudaFuncAttributeMaxDynamicSharedMemorySize, SMEM_TOT);
    gemm_mma<0><<<dim3(2, rbs), 256, SMEM_TOT>>>(
        h, W_fc, nullptr, b_fc, nullptr, nullptr, nullptr, px, N, FEAT);

    // K2: partial attention scores; 4 col-blocks of 64 attention channels each
    cudaFuncSetAttribute(gemm_mma<1>, cudaFuncAttributeMaxDynamicSharedMemorySize, SMEM_TOT);
    gemm_mma<1><<<dim3(4, rbs), 256, SMEM_TOT>>>(
        px, Wa, Wb, nullptr, ba, bb, Wc, pspart, N, HID);

    reduce_max_k<<<256, 256>>>(pspart, N, ppmax);
    finalize_max_k<<<1, 256>>>(ppmax, pmZ);
    pool_partial_k<<<256, 256>>>(px, pspart, pmZ, N, ppart, ppsum);
    pool_final_k<<<1, 256>>>(ppart, ppsum, pM);
    topk_kernel<<<1, 256>>>(pspart, N, ptop);
    final_kernel<<<1, 32>>>(pM, W_cls, b_cls, W_inst, b_inst, label, px, ptop,
                            (float*)d_out);
}